// round 1
// baseline (speedup 1.0000x reference)
#include <cuda_runtime.h>
#include <math.h>

// Problem constants (fixed by the dataset)
#define N_PTS 16384
#define HDIM  256
#define KSEL  7                     // k+1 smallest kept per row
#define NCHUNK 8                    // j-range split for occupancy
#define CHUNK (N_PTS / NCHUNK)      // 2048 points per chunk
#define ROWS_PER_BLK 256
#define MT 16                       // rows per block in the MLP kernel
#define HTOT 384                    // concat hidden: 256 (coord) + 128 (dist)

// Scratch (allocation-free rule: __device__ globals)
__device__ float g_part[N_PTS * NCHUNK * KSEL];  // per-(row,chunk) top-7 d2
__device__ float g_mean[N_PTS];                  // mean of 6 NN distances

// ---------------------------------------------------------------------------
// Kernel 1: partial top-7 squared distances per (row, j-chunk).
// One thread = one row, scanning one chunk of 2048 points held in shared.
// Top-7 kept as sorted-ascending register scalars; insertion is rare.
// ---------------------------------------------------------------------------
__global__ void __launch_bounds__(ROWS_PER_BLK)
knn_partial(const float2* __restrict__ pts) {
    __shared__ float2 tile[CHUNK];

    const int i     = blockIdx.x * ROWS_PER_BLK + threadIdx.x;
    const int cbase = blockIdx.y * CHUNK;

    // cooperative tile load (2048 float2 = 16 KB)
    for (int t = threadIdx.x; t < CHUNK; t += ROWS_PER_BLK)
        tile[t] = pts[cbase + t];
    __syncthreads();

    const float2 me = pts[i];
    const float xi = me.x, yi = me.y;

    float t0 = 1e30f, t1 = 1e30f, t2 = 1e30f, t3 = 1e30f,
          t4 = 1e30f, t5 = 1e30f, t6 = 1e30f;

    #pragma unroll 8
    for (int j = 0; j < CHUNK; ++j) {
        const float2 p = tile[j];          // broadcast LDS.64
        const float dx = p.x - xi;
        const float dy = p.y - yi;
        const float d2 = fmaf(dy, dy, dx * dx);
        if (d2 < t6) {                     // rare path (~54 hits per full row)
            t6 = d2;
            if (t6 < t5) { float tmp = t5; t5 = t6; t6 = tmp; }
            if (t5 < t4) { float tmp = t4; t4 = t5; t5 = tmp; }
            if (t4 < t3) { float tmp = t3; t3 = t4; t4 = tmp; }
            if (t3 < t2) { float tmp = t2; t2 = t3; t3 = tmp; }
            if (t2 < t1) { float tmp = t1; t1 = t2; t2 = tmp; }
            if (t1 < t0) { float tmp = t0; t0 = t1; t1 = tmp; }
        }
    }

    float* out = g_part + (size_t)(i * NCHUNK + blockIdx.y) * KSEL;
    out[0] = t0; out[1] = t1; out[2] = t2; out[3] = t3;
    out[4] = t4; out[5] = t5; out[6] = t6;
}

// ---------------------------------------------------------------------------
// Kernel 2: merge 8 partial top-7 lists -> global top-7 -> mean of the
// 6 smallest excluding the single minimum (the self-distance).
// ---------------------------------------------------------------------------
__global__ void __launch_bounds__(256)
knn_merge() {
    const int i = blockIdx.x * 256 + threadIdx.x;
    const float* p = g_part + (size_t)i * NCHUNK * KSEL;

    float t0 = 1e30f, t1 = 1e30f, t2 = 1e30f, t3 = 1e30f,
          t4 = 1e30f, t5 = 1e30f, t6 = 1e30f;

    #pragma unroll
    for (int s = 0; s < NCHUNK * KSEL; ++s) {
        const float d2 = p[s];
        if (d2 < t6) {
            t6 = d2;
            if (t6 < t5) { float tmp = t5; t5 = t6; t6 = tmp; }
            if (t5 < t4) { float tmp = t4; t4 = t5; t5 = tmp; }
            if (t4 < t3) { float tmp = t3; t3 = t4; t4 = tmp; }
            if (t3 < t2) { float tmp = t2; t2 = t3; t3 = tmp; }
            if (t2 < t1) { float tmp = t1; t1 = t2; t2 = tmp; }
            if (t1 < t0) { float tmp = t0; t0 = t1; t1 = tmp; }
        }
    }

    // sorted ascending: t0 is the minimum (self) -> dropped
    const float s1 = sqrtf(fmaxf(t1, 1e-12f));
    const float s2 = sqrtf(fmaxf(t2, 1e-12f));
    const float s3 = sqrtf(fmaxf(t3, 1e-12f));
    const float s4 = sqrtf(fmaxf(t4, 1e-12f));
    const float s5 = sqrtf(fmaxf(t5, 1e-12f));
    const float s6 = sqrtf(fmaxf(t6, 1e-12f));
    g_mean[i] = (s1 + s2 + s3 + s4 + s5 + s6) * (1.0f / 6.0f);
}

// ---------------------------------------------------------------------------
// Kernel 3: fused MLPs.
// Treats the two second-layer GEMMs as one GEMM against a concatenated
// 384-wide hidden vector: out = [h_coord ; h_dist] @ [W2 ; Wd2] + (b2+bd2).
// Block handles MT=16 rows; phase A builds the 16x384 hidden tile in shared,
// phase B: each thread owns one output column, float2 LDS over k.
// ---------------------------------------------------------------------------
__global__ void __launch_bounds__(256)
fused_mlp(const float2* __restrict__ coords,
          const float*  __restrict__ W1,  const float* __restrict__ b1,
          const float*  __restrict__ W2,  const float* __restrict__ b2,
          const float*  __restrict__ Wd1, const float* __restrict__ bd1,
          const float*  __restrict__ Wd2, const float* __restrict__ bd2,
          float* __restrict__ out) {
    __shared__ float hs[MT * HTOT];      // 24.5 KB

    const int r0 = blockIdx.x * MT;

    // Phase A: hidden activations (layer-1 + SiLU) for 16 rows x 384 features
    for (int e = threadIdx.x; e < MT * HTOT; e += 256) {
        const int m  = e / HTOT;
        const int kk = e - m * HTOT;
        const int r  = r0 + m;
        float v;
        if (kk < HDIM) {
            const float2 c = coords[r];
            v = fmaf(c.x, W1[kk], fmaf(c.y, W1[HDIM + kk], b1[kk]));
        } else {
            const int q = kk - HDIM;
            v = fmaf(g_mean[r], Wd1[q], bd1[q]);
        }
        hs[e] = v / (1.0f + __expf(-v));  // SiLU
    }
    __syncthreads();

    // Phase B: column-owned accumulation
    const int c = threadIdx.x;
    float acc[MT];
    const float binit = b2[c] + bd2[c];
    #pragma unroll
    for (int m = 0; m < MT; ++m) acc[m] = binit;

    // coord hidden (k = 0..255)
    #pragma unroll 4
    for (int k = 0; k < HDIM; k += 2) {
        const float w0 = W2[k * HDIM + c];
        const float w1 = W2[(k + 1) * HDIM + c];
        #pragma unroll
        for (int m = 0; m < MT; ++m) {
            const float2 h2 = *reinterpret_cast<const float2*>(&hs[m * HTOT + k]);
            acc[m] = fmaf(h2.x, w0, acc[m]);
            acc[m] = fmaf(h2.y, w1, acc[m]);
        }
    }
    // dist hidden (k = 0..127)
    #pragma unroll 4
    for (int k = 0; k < 128; k += 2) {
        const float w0 = Wd2[k * HDIM + c];
        const float w1 = Wd2[(k + 1) * HDIM + c];
        #pragma unroll
        for (int m = 0; m < MT; ++m) {
            const float2 h2 = *reinterpret_cast<const float2*>(&hs[m * HTOT + HDIM + k]);
            acc[m] = fmaf(h2.x, w0, acc[m]);
            acc[m] = fmaf(h2.y, w1, acc[m]);
        }
    }

    #pragma unroll
    for (int m = 0; m < MT; ++m)
        out[(size_t)(r0 + m) * HDIM + c] = acc[m];
}

// ---------------------------------------------------------------------------
// Launch. Inputs per metadata order:
// 0 coordinates (N,2) f32 | 1 W1 (2,256) | 2 b1 (256) | 3 W2 (256,256)
// 4 b2 (256) | 5 Wd1 (1,128) | 6 bd1 (128) | 7 Wd2 (128,256) | 8 bd2 (256)
// 9 k (unused; fixed at 6)
// ---------------------------------------------------------------------------
extern "C" void kernel_launch(void* const* d_in, const int* in_sizes, int n_in,
                              void* d_out, int out_size) {
    const float2* coords = (const float2*)d_in[0];
    const float*  W1     = (const float*)d_in[1];
    const float*  b1     = (const float*)d_in[2];
    const float*  W2     = (const float*)d_in[3];
    const float*  b2     = (const float*)d_in[4];
    const float*  Wd1    = (const float*)d_in[5];
    const float*  bd1    = (const float*)d_in[6];
    const float*  Wd2    = (const float*)d_in[7];
    const float*  bd2    = (const float*)d_in[8];
    float* out = (float*)d_out;

    dim3 g1(N_PTS / ROWS_PER_BLK, NCHUNK);     // 64 x 8 = 512 CTAs
    knn_partial<<<g1, ROWS_PER_BLK>>>(coords);
    knn_merge<<<N_PTS / 256, 256>>>();
    fused_mlp<<<N_PTS / MT, 256>>>(coords, W1, b1, W2, b2,
                                   Wd1, bd1, Wd2, bd2, out);
}